// round 14
// baseline (speedup 1.0000x reference)
#include <cuda_runtime.h>
#include <cuda_fp16.h>
#include <cuda_bf16.h>
#include <math.h>
#include <stdint.h>

#define L_ 4
#define H_ 8
#define D_ 512
#define HD_ 64
#define F_ 2048
#define V_ 32000
#define B_ 2
#define S_ 2048
#define M_ (B_ * S_)
#define QKV_ (3 * D_)

typedef unsigned short u16;

// ---------------- scratch ----------------
__device__ float g_x[M_ * D_];
__device__ float g_t[M_ * D_];
__device__ u16 g_qkvhi[M_ * QKV_], g_qkvlo[M_ * QKV_];
__device__ u16 g_xhi[M_ * D_], g_xlo[M_ * D_];
__device__ u16 g_ohi[M_ * D_], g_olo[M_ * D_];
__device__ u16 g_hhi[M_ * F_], g_hlo[M_ * F_];
__device__ u16 g_wq[QKV_ * D_];
__device__ u16 g_wo[D_ * D_];
__device__ u16 g_w1[F_ * D_];
__device__ u16 g_w2[D_ * F_];
__device__ u16 g_hw[V_ * D_];

// ---------------- fp16 split helpers ----------------
__device__ __forceinline__ u16 f16_hi(float v) {
    __half h = __float2half_rn(v);
    return *(u16*)&h;
}
__device__ __forceinline__ u16 f16_lo(float v) {
    __half h = __float2half_rn(v);
    float r = v - __half2float(h);
    __half l = __float2half_rn(r);
    return *(u16*)&l;
}
__device__ __forceinline__ uint32_t packh2(float a, float b) {
    __half2 t = __halves2half2(__float2half_rn(a), __float2half_rn(b));
    return *(uint32_t*)&t;
}
__device__ __forceinline__ uint32_t packh2_lo(float a, float b) {
    float ra = a - __half2float(__float2half_rn(a));
    float rb = b - __half2float(__float2half_rn(b));
    return packh2(ra, rb);
}

__device__ __forceinline__ uint32_t smem_u32(const void* p) {
    uint32_t a;
    asm("{ .reg .u64 t; cvta.to.shared.u64 t, %1; cvt.u32.u64 %0, t; }"
        : "=r"(a) : "l"(p));
    return a;
}

#define LDSM4(r, addr)                                                          \
    asm volatile("ldmatrix.sync.aligned.m8n8.x4.shared.b16 {%0,%1,%2,%3}, [%4];" \
                 : "=r"((r)[0]), "=r"((r)[1]), "=r"((r)[2]), "=r"((r)[3])        \
                 : "r"(addr))
#define LDSM2(r, addr)                                                          \
    asm volatile("ldmatrix.sync.aligned.m8n8.x2.shared.b16 {%0,%1}, [%2];"       \
                 : "=r"((r)[0]), "=r"((r)[1]) : "r"(addr))
#define LDSM2T(r, addr)                                                         \
    asm volatile("ldmatrix.sync.aligned.m8n8.x2.trans.shared.b16 {%0,%1}, [%2];" \
                 : "=r"((r)[0]), "=r"((r)[1]) : "r"(addr))
#define MMAH(c, a, b)                                                           \
    asm volatile("mma.sync.aligned.m16n8k16.row.col.f32.f16.f16.f32 "            \
                 "{%0,%1,%2,%3}, {%4,%5,%6,%7}, {%8,%9}, {%0,%1,%2,%3};"         \
                 : "+f"((c)[0]), "+f"((c)[1]), "+f"((c)[2]), "+f"((c)[3])        \
                 : "r"((a)[0]), "r"((a)[1]), "r"((a)[2]), "r"((a)[3]),           \
                   "r"((b)[0]), "r"((b)[1]))

// ==================== fp16 mma.sync GEMM (2-pass split-A) ====================
#define KSTRIDE 40
#define MAT_B  (128 * KSTRIDE * 2)
#define AH_OFF 0
#define AL_OFF (1 * MAT_B)
#define BH_OFF (2 * MAT_B)
#define STG_B  (3 * MAT_B)
#define NSTG   4
#define SMEM_GEMM (NSTG * STG_B)   // 122880 B

#define CP16(s, g)  asm volatile("cp.async.cg.shared.global [%0], [%1], 16;" :: "r"(s), "l"(g))
#define CP_COMMIT() asm volatile("cp.async.commit_group;" ::: "memory")
#define CP_WAIT2()  asm volatile("cp.async.wait_group 2;" ::: "memory")

template <bool SPLIT_OUT>
__global__ __launch_bounds__(256)
void gemm_f16(const u16* __restrict__ Ahi, const u16* __restrict__ Alo,
              const u16* __restrict__ Bh,
              const float* __restrict__ bias, float* __restrict__ Cf,
              u16* __restrict__ Chi, u16* __restrict__ Clo,
              int M, int N, int K, int relu) {
    extern __shared__ char sm[];
    uint32_t sb = smem_u32(sm);
    int tid = threadIdx.x, wid = tid >> 5, lane = tid & 31;
    int bm = blockIdx.y * 128, bn = blockIdx.x * 128;
    int warp_m = (wid & 1) * 64, warp_n = (wid >> 1) * 32;

    uint32_t a_off = (uint32_t)(warp_m + (lane & 15)) * KSTRIDE + ((lane >> 4) << 3);
    uint32_t b_off = (uint32_t)(warp_n + (lane & 7)) * KSTRIDE + (((lane >> 3) & 1) << 3);

    int c0i = tid * 2;
    int lrow0 = c0i >> 2, lc0 = (c0i & 3);
    int lrow1 = (c0i + 1) >> 2, lc1 = ((c0i + 1) & 3);

    float acc[4][4][4];
#pragma unroll
    for (int mi = 0; mi < 4; mi++)
#pragma unroll
        for (int ni = 0; ni < 4; ni++)
#pragma unroll
            for (int f = 0; f < 4; f++) acc[mi][ni][f] = 0.0f;

    int nt = K >> 5;

    auto load_stage = [&](int stg, int t) {
        uint32_t ss = sb + (uint32_t)stg * STG_B;
        int k0 = t << 5;
        uint32_t s0 = lrow0 * (KSTRIDE * 2) + lc0 * 16;
        uint32_t s1 = lrow1 * (KSTRIDE * 2) + lc1 * 16;
        size_t ga0 = (size_t)(bm + lrow0) * K + k0 + lc0 * 8;
        size_t ga1 = (size_t)(bm + lrow1) * K + k0 + lc1 * 8;
        size_t gb0 = (size_t)(bn + lrow0) * K + k0 + lc0 * 8;
        size_t gb1 = (size_t)(bn + lrow1) * K + k0 + lc1 * 8;
        CP16(ss + AH_OFF + s0, &Ahi[ga0]);
        CP16(ss + AH_OFF + s1, &Ahi[ga1]);
        CP16(ss + AL_OFF + s0, &Alo[ga0]);
        CP16(ss + AL_OFF + s1, &Alo[ga1]);
        CP16(ss + BH_OFF + s0, &Bh[gb0]);
        CP16(ss + BH_OFF + s1, &Bh[gb1]);
    };

#pragma unroll
    for (int s = 0; s < NSTG - 1; s++) {
        if (s < nt) load_stage(s, s);
        CP_COMMIT();
    }

    for (int t = 0; t < nt; t++) {
        CP_WAIT2();
        __syncthreads();

        uint32_t sa = sb + (uint32_t)(t & (NSTG - 1)) * STG_B;
#pragma unroll
        for (int ks = 0; ks < 2; ks++) {
            uint32_t aoff2 = (a_off + ks * 16) * 2;
            uint32_t boff2 = (b_off + ks * 16) * 2;
            uint32_t ah[4][4], al[4][4], bh[4][2];
#pragma unroll
            for (int mi = 0; mi < 4; mi++)
                LDSM4(ah[mi], sa + AH_OFF + aoff2 + mi * (16 * KSTRIDE * 2));
#pragma unroll
            for (int ni = 0; ni < 4; ni++)
                LDSM2(bh[ni], sa + BH_OFF + boff2 + ni * (8 * KSTRIDE * 2));
#pragma unroll
            for (int mi = 0; mi < 4; mi++)
#pragma unroll
                for (int ni = 0; ni < 4; ni++) MMAH(acc[mi][ni], ah[mi], bh[ni]);
#pragma unroll
            for (int mi = 0; mi < 4; mi++)
                LDSM4(al[mi], sa + AL_OFF + aoff2 + mi * (16 * KSTRIDE * 2));
#pragma unroll
            for (int mi = 0; mi < 4; mi++)
#pragma unroll
                for (int ni = 0; ni < 4; ni++) MMAH(acc[mi][ni], al[mi], bh[ni]);
        }

        if (t + NSTG - 1 < nt) load_stage((t + NSTG - 1) & (NSTG - 1), t + NSTG - 1);
        CP_COMMIT();
    }

    int gid = lane >> 2, tig = lane & 3;
#pragma unroll
    for (int mi = 0; mi < 4; mi++) {
        int r0 = bm + warp_m + mi * 16 + gid;
#pragma unroll
        for (int ni = 0; ni < 4; ni++) {
            int cg = bn + warp_n + ni * 8 + tig * 2;
            float c0 = acc[mi][ni][0], c1 = acc[mi][ni][1];
            float c2 = acc[mi][ni][2], c3 = acc[mi][ni][3];
            if (bias) {
                float bx = bias[cg], by = bias[cg + 1];
                c0 += bx; c1 += by; c2 += bx; c3 += by;
            }
            if (relu) {
                c0 = fmaxf(c0, 0.0f); c1 = fmaxf(c1, 0.0f);
                c2 = fmaxf(c2, 0.0f); c3 = fmaxf(c3, 0.0f);
            }
            if (SPLIT_OUT) {
                size_t i0 = (size_t)r0 * N + cg, i1 = (size_t)(r0 + 8) * N + cg;
                *(uint32_t*)&Chi[i0] = (uint32_t)f16_hi(c0) | ((uint32_t)f16_hi(c1) << 16);
                *(uint32_t*)&Clo[i0] = (uint32_t)f16_lo(c0) | ((uint32_t)f16_lo(c1) << 16);
                *(uint32_t*)&Chi[i1] = (uint32_t)f16_hi(c2) | ((uint32_t)f16_hi(c3) << 16);
                *(uint32_t*)&Clo[i1] = (uint32_t)f16_lo(c2) | ((uint32_t)f16_lo(c3) << 16);
            } else {
                *(float2*)&Cf[(size_t)r0 * N + cg] = make_float2(c0, c1);
                *(float2*)&Cf[(size_t)(r0 + 8) * N + cg] = make_float2(c2, c3);
            }
        }
    }
}

// ==================== tensor-core causal attention v3 ====================
// grid (S/128, B*H), 256 threads (8 warps x 16 queries).
// Pre-split qkv (hi/lo u16). V accessed via ldmatrix.trans (no transpose staging).
#define ASTR 72
#define Q_BUF (128 * ASTR)
#define K_BUF (64 * ASTR)
#define SMEM_ATT ((2 * Q_BUF + 4 * K_BUF) * 2)   // 73728 B

__global__ __launch_bounds__(256)
void attn_tc(const u16* __restrict__ qkvhi, const u16* __restrict__ qkvlo,
             u16* __restrict__ ohi, u16* __restrict__ olo) {
    extern __shared__ u16 sm16[];
    u16* Qh = sm16;
    u16* Ql = Qh + Q_BUF;
    u16* Kh = Ql + Q_BUF;
    u16* Kl = Kh + K_BUF;
    u16* Vh = Kl + K_BUF;
    u16* Vl = Vh + K_BUF;
    uint32_t sQh = smem_u32(Qh), sQl = smem_u32(Ql);
    uint32_t sKh = smem_u32(Kh), sKl = smem_u32(Kl);
    uint32_t sVh = smem_u32(Vh), sVl = smem_u32(Vl);

    int tid = threadIdx.x, wid = tid >> 5, lane = tid & 31;
    int gid = lane >> 2, tig = lane & 3;
    int bh = blockIdx.y;
    int b = bh / H_, h = bh % H_;
    int q0 = blockIdx.x * 128;

    // stage Q 128x64 (hi/lo), straight uint4 copies
    {
        const u16* qh_g = qkvhi + (size_t)(b * S_ + q0) * QKV_ + h * HD_;
        const u16* ql_g = qkvlo + (size_t)(b * S_ + q0) * QKV_ + h * HD_;
        for (int i = tid; i < 128 * 8; i += 256) {
            int r = i >> 3, c = (i & 7) * 8;
            *(uint4*)&Qh[r * ASTR + c] = *(const uint4*)&qh_g[(size_t)r * QKV_ + c];
            *(uint4*)&Ql[r * ASTR + c] = *(const uint4*)&ql_g[(size_t)r * QKV_ + c];
        }
    }

    int warp_m = wid * 16;
    uint32_t qa_off = (uint32_t)(warp_m + (lane & 15)) * ASTR + ((lane >> 4) << 3);
    uint32_t kb_off = (uint32_t)(lane & 7) * ASTR + (((lane >> 3) & 1) << 3);
    uint32_t vt_off = (uint32_t)(lane & 15) * ASTR;   // trans ldmatrix: rows=key

    uint32_t qh[4][4], ql[4][4];
    float m0 = -1e30f, m1 = -1e30f, l0 = 0.0f, l1 = 0.0f;
    float O[8][4];
#pragma unroll
    for (int n = 0; n < 8; n++)
#pragma unroll
        for (int f = 0; f < 4; f++) O[n][f] = 0.0f;

    int ntiles = blockIdx.x * 2 + 2;
    const float sc = 0.125f;

    for (int t = 0; t < ntiles; t++) {
        const u16* kh_g = qkvhi + (size_t)(b * S_ + t * 64) * QKV_ + D_ + h * HD_;
        const u16* kl_g = qkvlo + (size_t)(b * S_ + t * 64) * QKV_ + D_ + h * HD_;
        const u16* vh_g = qkvhi + (size_t)(b * S_ + t * 64) * QKV_ + 2 * D_ + h * HD_;
        const u16* vl_g = qkvlo + (size_t)(b * S_ + t * 64) * QKV_ + 2 * D_ + h * HD_;
        for (int i = tid; i < 64 * 8; i += 256) {
            int r = i >> 3, c = (i & 7) * 8;
            size_t g = (size_t)r * QKV_ + c;
            int so = r * ASTR + c;
            *(uint4*)&Kh[so] = *(const uint4*)&kh_g[g];
            *(uint4*)&Kl[so] = *(const uint4*)&kl_g[g];
            *(uint4*)&Vh[so] = *(const uint4*)&vh_g[g];
            *(uint4*)&Vl[so] = *(const uint4*)&vl_g[g];
        }
        __syncthreads();

        if (t == 0) {
#pragma unroll
            for (int ks = 0; ks < 4; ks++) {
                LDSM4(qh[ks], sQh + (qa_off + ks * 16) * 2);
                LDSM4(ql[ks], sQl + (qa_off + ks * 16) * 2);
            }
        }

        // skip tiles fully above this warp's rows (causal)
        if (t * 64 <= q0 + warp_m + 15) {
            // S = Q K^T  (3 passes)
            float s[8][4];
#pragma unroll
            for (int n = 0; n < 8; n++) {
#pragma unroll
                for (int f = 0; f < 4; f++) s[n][f] = 0.0f;
#pragma unroll
                for (int ks = 0; ks < 4; ks++) {
                    uint32_t kh2[2], kl2[2];
                    uint32_t ko = (kb_off + (uint32_t)n * 8 * ASTR + ks * 16) * 2;
                    LDSM2(kh2, sKh + ko);
                    LDSM2(kl2, sKl + ko);
                    MMAH(s[n], qh[ks], kh2);
                    MMAH(s[n], ql[ks], kh2);
                    MMAH(s[n], qh[ks], kl2);
                }
            }

            // scale + causal mask
            int qg0 = q0 + warp_m + gid, qg1 = qg0 + 8;
#pragma unroll
            for (int n = 0; n < 8; n++) {
                int kc = t * 64 + n * 8 + 2 * tig;
                s[n][0] = (kc > qg0) ? -1e30f : s[n][0] * sc;
                s[n][1] = (kc + 1 > qg0) ? -1e30f : s[n][1] * sc;
                s[n][2] = (kc > qg1) ? -1e30f : s[n][2] * sc;
                s[n][3] = (kc + 1 > qg1) ? -1e30f : s[n][3] * sc;
            }

            float tm0 = -1e30f, tm1 = -1e30f;
#pragma unroll
            for (int n = 0; n < 8; n++) {
                tm0 = fmaxf(tm0, fmaxf(s[n][0], s[n][1]));
                tm1 = fmaxf(tm1, fmaxf(s[n][2], s[n][3]));
            }
            tm0 = fmaxf(tm0, __shfl_xor_sync(0xFFFFFFFF, tm0, 1));
            tm0 = fmaxf(tm0, __shfl_xor_sync(0xFFFFFFFF, tm0, 2));
            tm1 = fmaxf(tm1, __shfl_xor_sync(0xFFFFFFFF, tm1, 1));
            tm1 = fmaxf(tm1, __shfl_xor_sync(0xFFFFFFFF, tm1, 2));

            float mn0 = fmaxf(m0, tm0), mn1 = fmaxf(m1, tm1);
            float corr0 = __expf(m0 - mn0), corr1 = __expf(m1 - mn1);
            m0 = mn0; m1 = mn1;

            float sum0 = 0.0f, sum1 = 0.0f;
#pragma unroll
            for (int n = 0; n < 8; n++) {
                s[n][0] = __expf(s[n][0] - mn0);
                s[n][1] = __expf(s[n][1] - mn0);
                s[n][2] = __expf(s[n][2] - mn1);
                s[n][3] = __expf(s[n][3] - mn1);
                sum0 += s[n][0] + s[n][1];
                sum1 += s[n][2] + s[n][3];
            }
            sum0 += __shfl_xor_sync(0xFFFFFFFF, sum0, 1);
            sum0 += __shfl_xor_sync(0xFFFFFFFF, sum0, 2);
            sum1 += __shfl_xor_sync(0xFFFFFFFF, sum1, 1);
            sum1 += __shfl_xor_sync(0xFFFFFFFF, sum1, 2);
            l0 = l0 * corr0 + sum0;
            l1 = l1 * corr1 + sum1;

#pragma unroll
            for (int n = 0; n < 8; n++) {
                O[n][0] *= corr0; O[n][1] *= corr0;
                O[n][2] *= corr1; O[n][3] *= corr1;
            }

            uint32_t ph[8][2], pl[8][2];
#pragma unroll
            for (int n = 0; n < 8; n++) {
                ph[n][0] = packh2(s[n][0], s[n][1]);
                ph[n][1] = packh2(s[n][2], s[n][3]);
                pl[n][0] = packh2_lo(s[n][0], s[n][1]);
                pl[n][1] = packh2_lo(s[n][2], s[n][3]);
            }

            // O += P V (3 passes), V via ldmatrix.trans from [key][hd]
#pragma unroll
            for (int n = 0; n < 8; n++) {
#pragma unroll
                for (int kt = 0; kt < 4; kt++) {
                    uint32_t vh2[2], vl2[2];
                    uint32_t vo = (vt_off + (uint32_t)kt * 16 * ASTR + n * 8) * 2;
                    LDSM2T(vh2, sVh + vo);
                    LDSM2T(vl2, sVl + vo);
                    uint32_t aH[4] = {ph[2 * kt][0], ph[2 * kt][1],
                                      ph[2 * kt + 1][0], ph[2 * kt + 1][1]};
                    uint32_t aL[4] = {pl[2 * kt][0], pl[2 * kt][1],
                                      pl[2 * kt + 1][0], pl[2 * kt + 1][1]};
                    MMAH(O[n], aH, vh2);
                    MMAH(O[n], aL, vh2);
                    MMAH(O[n], aH, vl2);
                }
            }
        }
        __syncthreads();
    }

    float inv0 = 1.0f / l0, inv1 = 1.0f / l1;
    int r0 = b * S_ + q0 + warp_m + gid;
#pragma unroll
    for (int n = 0; n < 8; n++) {
        float o0 = O[n][0] * inv0, o1 = O[n][1] * inv0;
        float o2 = O[n][2] * inv1, o3 = O[n][3] * inv1;
        size_t i0 = (size_t)r0 * D_ + h * HD_ + n * 8 + 2 * tig;
        size_t i1 = (size_t)(r0 + 8) * D_ + h * HD_ + n * 8 + 2 * tig;
        *(uint32_t*)&ohi[i0] = (uint32_t)f16_hi(o0) | ((uint32_t)f16_hi(o1) << 16);
        *(uint32_t*)&olo[i0] = (uint32_t)f16_lo(o0) | ((uint32_t)f16_lo(o1) << 16);
        *(uint32_t*)&ohi[i1] = (uint32_t)f16_hi(o2) | ((uint32_t)f16_hi(o3) << 16);
        *(uint32_t*)&olo[i1] = (uint32_t)f16_lo(o2) | ((uint32_t)f16_lo(o3) << 16);
    }
}

// ---------------- embedding + PE (+ split) ----------------
__global__ void embed_kernel(const int* __restrict__ tokens,
                             const float* __restrict__ emb,
                             float* __restrict__ x,
                             u16* __restrict__ xhi, u16* __restrict__ xlo) {
    int i = blockIdx.x * blockDim.x + threadIdx.x;
    if (i >= M_ * D_) return;
    int m = i / D_, d = i % D_;
    int s = m % S_;
    int tok = tokens[m];
    float expo = (float)(d & ~1) * (-logf(10000.0f) / (float)D_);
    float ang = (float)s * expf(expo);
    float pe = (d & 1) ? cosf(ang) : sinf(ang);
    float v = emb[tok * D_ + d] + pe;
    x[i] = v;
    xhi[i] = f16_hi(v);
    xlo[i] = f16_lo(v);
}

// ---------------- repack QKV weights -> [3D][D] fp16 ----------------
__global__ void repack_qkvT_h(const float* __restrict__ Wq,
                              const float* __restrict__ Wk,
                              const float* __restrict__ Wv,
                              u16* __restrict__ w) {
    int i = blockIdx.x * blockDim.x + threadIdx.x;
    if (i >= D_ * D_) return;
    int n = i / D_, d = i % D_;
    int h = n / HD_, e = n % HD_;
    int src = h * D_ * HD_ + d * HD_ + e;
    size_t iq = (size_t)n * D_ + d;
    w[iq] = f16_hi(Wq[src]);
    w[iq + (size_t)D_ * D_] = f16_hi(Wk[src]);
    w[iq + (size_t)2 * D_ * D_] = f16_hi(Wv[src]);
}

// ---------------- transpose to fp16 ----------------
__global__ void transpose_h(const float* __restrict__ in,
                            u16* __restrict__ o, int R, int C) {
    __shared__ float tile[32][33];
    int c0 = blockIdx.x * 32, r0 = blockIdx.y * 32;
    int x = threadIdx.x, y = threadIdx.y;
#pragma unroll
    for (int i = 0; i < 32; i += 8)
        tile[y + i][x] = in[(size_t)(r0 + y + i) * C + c0 + x];
    __syncthreads();
#pragma unroll
    for (int i = 0; i < 32; i += 8)
        o[(size_t)(c0 + y + i) * R + r0 + x] = f16_hi(tile[x][y + i]);
}

// ---------------- plain fp16 convert (head_W) ----------------
__global__ void conv_h(const float* __restrict__ in, u16* __restrict__ o, int n) {
    int i = blockIdx.x * blockDim.x + threadIdx.x;
    if (i >= n) return;
    o[i] = f16_hi(in[i]);
}

// ---------------- residual + LayerNorm (+ split) ----------------
__global__ __launch_bounds__(128)
void ln_kernel(float* __restrict__ x, const float* __restrict__ delta,
               const float* __restrict__ gamma, const float* __restrict__ beta,
               u16* __restrict__ xhi, u16* __restrict__ xlo) {
    int row = blockIdx.x;
    int tid = threadIdx.x;
    __shared__ float red[128];

    float v[4];
    float s = 0.0f;
#pragma unroll
    for (int i = 0; i < 4; i++) {
        int d = i * 128 + tid;
        float t = x[(size_t)row * D_ + d];
        if (delta) t += delta[(size_t)row * D_ + d];
        v[i] = t;
        s += t;
    }
    red[tid] = s;
    __syncthreads();
    for (int off = 64; off > 0; off >>= 1) {
        if (tid < off) red[tid] += red[tid + off];
        __syncthreads();
    }
    float mean = red[0] * (1.0f / D_);
    __syncthreads();

    float s2 = 0.0f;
#pragma unroll
    for (int i = 0; i < 4; i++) {
        float dv = v[i] - mean;
        s2 += dv * dv;
    }
    red[tid] = s2;
    __syncthreads();
    for (int off = 64; off > 0; off >>= 1) {
        if (tid < off) red[tid] += red[tid + off];
        __syncthreads();
    }
    float var = red[0] * (1.0f / D_);
    float rstd = rsqrtf(var + 1e-5f);
#pragma unroll
    for (int i = 0; i < 4; i++) {
        int d = i * 128 + tid;
        float o = (v[i] - mean) * rstd * gamma[d] + beta[d];
        size_t idx = (size_t)row * D_ + d;
        x[idx] = o;
        xhi[idx] = f16_hi(o);
        xlo[idx] = f16_lo(o);
    }
}

// ---------------- launch ----------------
extern "C" void kernel_launch(void* const* d_in, const int* in_sizes, int n_in,
                              void* d_out, int out_size) {
    const int* tokens    = (const int*)d_in[0];
    const float* emb     = (const float*)d_in[1];
    const float* Wq      = (const float*)d_in[2];
    const float* Wk      = (const float*)d_in[3];
    const float* Wv      = (const float*)d_in[4];
    const float* Wo      = (const float*)d_in[5];
    const float* bo      = (const float*)d_in[6];
    const float* ln1_g   = (const float*)d_in[7];
    const float* ln1_b   = (const float*)d_in[8];
    const float* W1      = (const float*)d_in[9];
    const float* b1      = (const float*)d_in[10];
    const float* W2      = (const float*)d_in[11];
    const float* b2      = (const float*)d_in[12];
    const float* ln2_g   = (const float*)d_in[13];
    const float* ln2_b   = (const float*)d_in[14];
    const float* lnf_g   = (const float*)d_in[15];
    const float* lnf_b   = (const float*)d_in[16];
    const float* head_W  = (const float*)d_in[17];
    float* out = (float*)d_out;

    float *x, *t;
    u16 *qkvhi, *qkvlo, *xhi, *xlo, *ohi, *olo, *hhi, *hlo;
    u16 *wq, *wo, *w1, *w2, *hw;
    cudaGetSymbolAddress((void**)&x, g_x);
    cudaGetSymbolAddress((void**)&t, g_t);
    cudaGetSymbolAddress((void**)&qkvhi, g_qkvhi);
    cudaGetSymbolAddress((void**)&qkvlo, g_qkvlo);
    cudaGetSymbolAddress((void**)&xhi, g_xhi);
    cudaGetSymbolAddress((void**)&xlo, g_xlo);
    cudaGetSymbolAddress((void**)&ohi, g_ohi);
    cudaGetSymbolAddress((void**)&olo, g_olo);
    cudaGetSymbolAddress((void**)&hhi, g_hhi);
    cudaGetSymbolAddress((void**)&hlo, g_hlo);
    cudaGetSymbolAddress((void**)&wq, g_wq);
    cudaGetSymbolAddress((void**)&wo, g_wo);
    cudaGetSymbolAddress((void**)&w1, g_w1);
    cudaGetSymbolAddress((void**)&w2, g_w2);
    cudaGetSymbolAddress((void**)&hw, g_hw);

    cudaFuncSetAttribute(gemm_f16<false>, cudaFuncAttributeMaxDynamicSharedMemorySize, SMEM_GEMM);
    cudaFuncSetAttribute(gemm_f16<true>,  cudaFuncAttributeMaxDynamicSharedMemorySize, SMEM_GEMM);
    cudaFuncSetAttribute(attn_tc, cudaFuncAttributeMaxDynamicSharedMemorySize, SMEM_ATT);

    embed_kernel<<<(M_ * D_ + 255) / 256, 256>>>(tokens, emb, x, xhi, xlo);
    conv_h<<<(V_ * D_ + 255) / 256, 256>>>(head_W, hw, V_ * D_);

    dim3 gQKV(QKV_ / 128, M_ / 128);
    dim3 gD(D_ / 128, M_ / 128);
    dim3 gF(F_ / 128, M_ / 128);
    dim3 gV(V_ / 128, M_ / 128);
    dim3 gAttn(S_ / 128, B_ * H_);
    dim3 tb(32, 8);

    for (int l = 0; l < L_; l++) {
        const float* Wq_l = Wq + (size_t)l * H_ * D_ * HD_;
        const float* Wk_l = Wk + (size_t)l * H_ * D_ * HD_;
        const float* Wv_l = Wv + (size_t)l * H_ * D_ * HD_;
        const float* Wo_l = Wo + (size_t)l * D_ * D_;
        const float* bo_l = bo + (size_t)l * D_;
        const float* W1_l = W1 + (size_t)l * D_ * F_;
        const float* b1_l = b1 + (size_t)l * F_;
        const float* W2_l = W2 + (size_t)l * F_ * D_;
        const float* b2_l = b2 + (size_t)l * D_;

        repack_qkvT_h<<<(D_ * D_ + 255) / 256, 256>>>(Wq_l, Wk_l, Wv_l, wq);
        transpose_h<<<dim3(D_ / 32, D_ / 32), tb>>>(Wo_l, wo, D_, D_);
        transpose_h<<<dim3(F_ / 32, D_ / 32), tb>>>(W1_l, w1, D_, F_);
        transpose_h<<<dim3(D_ / 32, F_ / 32), tb>>>(W2_l, w2, F_, D_);

        gemm_f16<true><<<gQKV, 256, SMEM_GEMM>>>(xhi, xlo, wq, nullptr,
                                                 nullptr, qkvhi, qkvlo, M_, QKV_, D_, 0);

        attn_tc<<<gAttn, 256, SMEM_ATT>>>(qkvhi, qkvlo, ohi, olo);

        gemm_f16<false><<<gD, 256, SMEM_GEMM>>>(ohi, olo, wo, bo_l,
                                                t, nullptr, nullptr, M_, D_, D_, 0);
        ln_kernel<<<M_, 128>>>(x, t, ln1_g + (size_t)l * D_, ln1_b + (size_t)l * D_, xhi, xlo);

        gemm_f16<true><<<gF, 256, SMEM_GEMM>>>(xhi, xlo, w1, b1_l,
                                               nullptr, hhi, hlo, M_, F_, D_, 1);
        gemm_f16<false><<<gD, 256, SMEM_GEMM>>>(hhi, hlo, w2, b2_l,
                                                t, nullptr, nullptr, M_, D_, F_, 0);
        ln_kernel<<<M_, 128>>>(x, t, ln2_g + (size_t)l * D_, ln2_b + (size_t)l * D_, xhi, xlo);
    }

    ln_kernel<<<M_, 128>>>(x, nullptr, lnf_g, lnf_b, xhi, xlo);
    gemm_f16<false><<<gV, 256, SMEM_GEMM>>>(xhi, xlo, hw, nullptr,
                                            out, nullptr, nullptr, M_, V_, D_, 0);
}

// round 16
// speedup vs baseline: 1.1646x; 1.1646x over previous
#include <cuda_runtime.h>
#include <cuda_fp16.h>
#include <cuda_bf16.h>
#include <math.h>
#include <stdint.h>

#define L_ 4
#define H_ 8
#define D_ 512
#define HD_ 64
#define F_ 2048
#define V_ 32000
#define B_ 2
#define S_ 2048
#define M_ (B_ * S_)
#define QKV_ (3 * D_)

typedef unsigned short u16;

// ---------------- scratch ----------------
__device__ float g_x[M_ * D_];
__device__ float g_t[M_ * D_];
__device__ u16 g_qkvhi[M_ * QKV_], g_qkvlo[M_ * QKV_];
__device__ u16 g_xhi[M_ * D_], g_xlo[M_ * D_];
__device__ u16 g_ohi[M_ * D_], g_olo[M_ * D_];
__device__ u16 g_hhi[M_ * F_], g_hlo[M_ * F_];
__device__ u16 g_wq[QKV_ * D_];
__device__ u16 g_wo[D_ * D_];
__device__ u16 g_w1[F_ * D_];
__device__ u16 g_w2[D_ * F_];
__device__ u16 g_hw[V_ * D_];

// ---------------- fp16 split helpers ----------------
__device__ __forceinline__ u16 f16_hi(float v) {
    __half h = __float2half_rn(v);
    return *(u16*)&h;
}
__device__ __forceinline__ u16 f16_lo(float v) {
    __half h = __float2half_rn(v);
    float r = v - __half2float(h);
    __half l = __float2half_rn(r);
    return *(u16*)&l;
}
__device__ __forceinline__ uint32_t packh2(float a, float b) {
    __half2 t = __halves2half2(__float2half_rn(a), __float2half_rn(b));
    return *(uint32_t*)&t;
}
__device__ __forceinline__ uint32_t packh2_lo(float a, float b) {
    float ra = a - __half2float(__float2half_rn(a));
    float rb = b - __half2float(__float2half_rn(b));
    return packh2(ra, rb);
}

__device__ __forceinline__ uint32_t smem_u32(const void* p) {
    uint32_t a;
    asm("{ .reg .u64 t; cvta.to.shared.u64 t, %1; cvt.u32.u64 %0, t; }"
        : "=r"(a) : "l"(p));
    return a;
}

#define LDSM4(r, addr)                                                          \
    asm volatile("ldmatrix.sync.aligned.m8n8.x4.shared.b16 {%0,%1,%2,%3}, [%4];" \
                 : "=r"((r)[0]), "=r"((r)[1]), "=r"((r)[2]), "=r"((r)[3])        \
                 : "r"(addr))
#define LDSM2(r, addr)                                                          \
    asm volatile("ldmatrix.sync.aligned.m8n8.x2.shared.b16 {%0,%1}, [%2];"       \
                 : "=r"((r)[0]), "=r"((r)[1]) : "r"(addr))
#define LDSM2T(r, addr)                                                         \
    asm volatile("ldmatrix.sync.aligned.m8n8.x2.trans.shared.b16 {%0,%1}, [%2];" \
                 : "=r"((r)[0]), "=r"((r)[1]) : "r"(addr))
#define MMAH(c, a, b)                                                           \
    asm volatile("mma.sync.aligned.m16n8k16.row.col.f32.f16.f16.f32 "            \
                 "{%0,%1,%2,%3}, {%4,%5,%6,%7}, {%8,%9}, {%0,%1,%2,%3};"         \
                 : "+f"((c)[0]), "+f"((c)[1]), "+f"((c)[2]), "+f"((c)[3])        \
                 : "r"((a)[0]), "r"((a)[1]), "r"((a)[2]), "r"((a)[3]),           \
                   "r"((b)[0]), "r"((b)[1]))

// ==================== fp16 mma.sync GEMM ====================
// TWO_PASS: C = (Ahi+Alo) @ Bh^T.  !TWO_PASS: C = Ahi @ Bh^T (head GEMM).
#define KSTRIDE 40
#define MAT_B  (128 * KSTRIDE * 2)
#define AH_OFF 0
#define AL_OFF (1 * MAT_B)
#define BH_OFF (2 * MAT_B)
#define STG_B  (3 * MAT_B)
#define NSTG   4
#define SMEM_GEMM (NSTG * STG_B)   // 122880 B

#define CP16(s, g)  asm volatile("cp.async.cg.shared.global [%0], [%1], 16;" :: "r"(s), "l"(g))
#define CP_COMMIT() asm volatile("cp.async.commit_group;" ::: "memory")
#define CP_WAIT2()  asm volatile("cp.async.wait_group 2;" ::: "memory")

template <bool SPLIT_OUT, bool TWO_PASS>
__global__ __launch_bounds__(256)
void gemm_f16(const u16* __restrict__ Ahi, const u16* __restrict__ Alo,
              const u16* __restrict__ Bh,
              const float* __restrict__ bias, float* __restrict__ Cf,
              u16* __restrict__ Chi, u16* __restrict__ Clo,
              int M, int N, int K, int relu) {
    extern __shared__ char sm[];
    uint32_t sb = smem_u32(sm);
    int tid = threadIdx.x, wid = tid >> 5, lane = tid & 31;
    int bm = blockIdx.y * 128, bn = blockIdx.x * 128;
    int warp_m = (wid & 1) * 64, warp_n = (wid >> 1) * 32;

    uint32_t a_off = (uint32_t)(warp_m + (lane & 15)) * KSTRIDE + ((lane >> 4) << 3);
    uint32_t b_off = (uint32_t)(warp_n + (lane & 7)) * KSTRIDE + (((lane >> 3) & 1) << 3);

    int c0i = tid * 2;
    int lrow0 = c0i >> 2, lc0 = (c0i & 3);
    int lrow1 = (c0i + 1) >> 2, lc1 = ((c0i + 1) & 3);

    float acc[4][4][4];
#pragma unroll
    for (int mi = 0; mi < 4; mi++)
#pragma unroll
        for (int ni = 0; ni < 4; ni++)
#pragma unroll
            for (int f = 0; f < 4; f++) acc[mi][ni][f] = 0.0f;

    int nt = K >> 5;

    auto load_stage = [&](int stg, int t) {
        uint32_t ss = sb + (uint32_t)stg * STG_B;
        int k0 = t << 5;
        uint32_t s0 = lrow0 * (KSTRIDE * 2) + lc0 * 16;
        uint32_t s1 = lrow1 * (KSTRIDE * 2) + lc1 * 16;
        size_t ga0 = (size_t)(bm + lrow0) * K + k0 + lc0 * 8;
        size_t ga1 = (size_t)(bm + lrow1) * K + k0 + lc1 * 8;
        size_t gb0 = (size_t)(bn + lrow0) * K + k0 + lc0 * 8;
        size_t gb1 = (size_t)(bn + lrow1) * K + k0 + lc1 * 8;
        CP16(ss + AH_OFF + s0, &Ahi[ga0]);
        CP16(ss + AH_OFF + s1, &Ahi[ga1]);
        if (TWO_PASS) {
            CP16(ss + AL_OFF + s0, &Alo[ga0]);
            CP16(ss + AL_OFF + s1, &Alo[ga1]);
        }
        CP16(ss + BH_OFF + s0, &Bh[gb0]);
        CP16(ss + BH_OFF + s1, &Bh[gb1]);
    };

#pragma unroll
    for (int s = 0; s < NSTG - 1; s++) {
        if (s < nt) load_stage(s, s);
        CP_COMMIT();
    }

    for (int t = 0; t < nt; t++) {
        CP_WAIT2();
        __syncthreads();

        uint32_t sa = sb + (uint32_t)(t & (NSTG - 1)) * STG_B;
#pragma unroll
        for (int ks = 0; ks < 2; ks++) {
            uint32_t aoff2 = (a_off + ks * 16) * 2;
            uint32_t boff2 = (b_off + ks * 16) * 2;
            uint32_t ah[4][4], al[4][4], bh[4][2];
#pragma unroll
            for (int mi = 0; mi < 4; mi++)
                LDSM4(ah[mi], sa + AH_OFF + aoff2 + mi * (16 * KSTRIDE * 2));
#pragma unroll
            for (int ni = 0; ni < 4; ni++)
                LDSM2(bh[ni], sa + BH_OFF + boff2 + ni * (8 * KSTRIDE * 2));
#pragma unroll
            for (int mi = 0; mi < 4; mi++)
#pragma unroll
                for (int ni = 0; ni < 4; ni++) MMAH(acc[mi][ni], ah[mi], bh[ni]);
            if (TWO_PASS) {
#pragma unroll
                for (int mi = 0; mi < 4; mi++)
                    LDSM4(al[mi], sa + AL_OFF + aoff2 + mi * (16 * KSTRIDE * 2));
#pragma unroll
                for (int mi = 0; mi < 4; mi++)
#pragma unroll
                    for (int ni = 0; ni < 4; ni++) MMAH(acc[mi][ni], al[mi], bh[ni]);
            }
        }

        if (t + NSTG - 1 < nt) load_stage((t + NSTG - 1) & (NSTG - 1), t + NSTG - 1);
        CP_COMMIT();
    }

    int gid = lane >> 2, tig = lane & 3;
#pragma unroll
    for (int mi = 0; mi < 4; mi++) {
        int r0 = bm + warp_m + mi * 16 + gid;
#pragma unroll
        for (int ni = 0; ni < 4; ni++) {
            int cg = bn + warp_n + ni * 8 + tig * 2;
            float c0 = acc[mi][ni][0], c1 = acc[mi][ni][1];
            float c2 = acc[mi][ni][2], c3 = acc[mi][ni][3];
            if (bias) {
                float bx = bias[cg], by = bias[cg + 1];
                c0 += bx; c1 += by; c2 += bx; c3 += by;
            }
            if (relu) {
                c0 = fmaxf(c0, 0.0f); c1 = fmaxf(c1, 0.0f);
                c2 = fmaxf(c2, 0.0f); c3 = fmaxf(c3, 0.0f);
            }
            if (SPLIT_OUT) {
                size_t i0 = (size_t)r0 * N + cg, i1 = (size_t)(r0 + 8) * N + cg;
                *(uint32_t*)&Chi[i0] = (uint32_t)f16_hi(c0) | ((uint32_t)f16_hi(c1) << 16);
                *(uint32_t*)&Clo[i0] = (uint32_t)f16_lo(c0) | ((uint32_t)f16_lo(c1) << 16);
                *(uint32_t*)&Chi[i1] = (uint32_t)f16_hi(c2) | ((uint32_t)f16_hi(c3) << 16);
                *(uint32_t*)&Clo[i1] = (uint32_t)f16_lo(c2) | ((uint32_t)f16_lo(c3) << 16);
            } else {
                *(float2*)&Cf[(size_t)r0 * N + cg] = make_float2(c0, c1);
                *(float2*)&Cf[(size_t)(r0 + 8) * N + cg] = make_float2(c2, c3);
            }
        }
    }
}

// ==================== tensor-core causal attention ====================
// grid (S/128, B*H), 256 threads (8 warps x 16 queries).
#define ASTR 72
#define Q_BUF (128 * ASTR)
#define K_BUF (64 * ASTR)
#define SMEM_ATT ((2 * Q_BUF + 4 * K_BUF) * 2)   // 73728 B

__global__ __launch_bounds__(256)
void attn_tc(const u16* __restrict__ qkvhi, const u16* __restrict__ qkvlo,
             u16* __restrict__ ohi, u16* __restrict__ olo) {
    extern __shared__ u16 sm16[];
    u16* Qh = sm16;
    u16* Ql = Qh + Q_BUF;
    u16* Kh = Ql + Q_BUF;
    u16* Kl = Kh + K_BUF;
    u16* Vh = Kl + K_BUF;
    u16* Vl = Vh + K_BUF;
    uint32_t sQh = smem_u32(Qh), sQl = smem_u32(Ql);
    uint32_t sKh = smem_u32(Kh), sKl = smem_u32(Kl);
    uint32_t sVh = smem_u32(Vh), sVl = smem_u32(Vl);

    int tid = threadIdx.x, wid = tid >> 5, lane = tid & 31;
    int gid = lane >> 2, tig = lane & 3;
    int bh = blockIdx.y;
    int b = bh / H_, h = bh % H_;
    int q0 = blockIdx.x * 128;

    {
        const u16* qh_g = qkvhi + (size_t)(b * S_ + q0) * QKV_ + h * HD_;
        const u16* ql_g = qkvlo + (size_t)(b * S_ + q0) * QKV_ + h * HD_;
        for (int i = tid; i < 128 * 8; i += 256) {
            int r = i >> 3, c = (i & 7) * 8;
            *(uint4*)&Qh[r * ASTR + c] = *(const uint4*)&qh_g[(size_t)r * QKV_ + c];
            *(uint4*)&Ql[r * ASTR + c] = *(const uint4*)&ql_g[(size_t)r * QKV_ + c];
        }
    }

    int warp_m = wid * 16;
    uint32_t qa_off = (uint32_t)(warp_m + (lane & 15)) * ASTR + ((lane >> 4) << 3);
    uint32_t kb_off = (uint32_t)(lane & 7) * ASTR + (((lane >> 3) & 1) << 3);
    uint32_t vt_off = (uint32_t)(lane & 15) * ASTR;

    uint32_t qh[4][4], ql[4][4];
    float m0 = -1e30f, m1 = -1e30f, l0 = 0.0f, l1 = 0.0f;
    float O[8][4];
#pragma unroll
    for (int n = 0; n < 8; n++)
#pragma unroll
        for (int f = 0; f < 4; f++) O[n][f] = 0.0f;

    int ntiles = blockIdx.x * 2 + 2;
    const float sc = 0.125f;

    for (int t = 0; t < ntiles; t++) {
        const u16* kh_g = qkvhi + (size_t)(b * S_ + t * 64) * QKV_ + D_ + h * HD_;
        const u16* kl_g = qkvlo + (size_t)(b * S_ + t * 64) * QKV_ + D_ + h * HD_;
        const u16* vh_g = qkvhi + (size_t)(b * S_ + t * 64) * QKV_ + 2 * D_ + h * HD_;
        const u16* vl_g = qkvlo + (size_t)(b * S_ + t * 64) * QKV_ + 2 * D_ + h * HD_;
        for (int i = tid; i < 64 * 8; i += 256) {
            int r = i >> 3, c = (i & 7) * 8;
            size_t g = (size_t)r * QKV_ + c;
            int so = r * ASTR + c;
            *(uint4*)&Kh[so] = *(const uint4*)&kh_g[g];
            *(uint4*)&Kl[so] = *(const uint4*)&kl_g[g];
            *(uint4*)&Vh[so] = *(const uint4*)&vh_g[g];
            *(uint4*)&Vl[so] = *(const uint4*)&vl_g[g];
        }
        __syncthreads();

        if (t == 0) {
#pragma unroll
            for (int ks = 0; ks < 4; ks++) {
                LDSM4(qh[ks], sQh + (qa_off + ks * 16) * 2);
                LDSM4(ql[ks], sQl + (qa_off + ks * 16) * 2);
            }
        }

        if (t * 64 <= q0 + warp_m + 15) {
            float s[8][4];
#pragma unroll
            for (int n = 0; n < 8; n++) {
#pragma unroll
                for (int f = 0; f < 4; f++) s[n][f] = 0.0f;
#pragma unroll
                for (int ks = 0; ks < 4; ks++) {
                    uint32_t kh2[2], kl2[2];
                    uint32_t ko = (kb_off + (uint32_t)n * 8 * ASTR + ks * 16) * 2;
                    LDSM2(kh2, sKh + ko);
                    LDSM2(kl2, sKl + ko);
                    MMAH(s[n], qh[ks], kh2);
                    MMAH(s[n], ql[ks], kh2);
                    MMAH(s[n], qh[ks], kl2);
                }
            }

            int qg0 = q0 + warp_m + gid, qg1 = qg0 + 8;
#pragma unroll
            for (int n = 0; n < 8; n++) {
                int kc = t * 64 + n * 8 + 2 * tig;
                s[n][0] = (kc > qg0) ? -1e30f : s[n][0] * sc;
                s[n][1] = (kc + 1 > qg0) ? -1e30f : s[n][1] * sc;
                s[n][2] = (kc > qg1) ? -1e30f : s[n][2] * sc;
                s[n][3] = (kc + 1 > qg1) ? -1e30f : s[n][3] * sc;
            }

            float tm0 = -1e30f, tm1 = -1e30f;
#pragma unroll
            for (int n = 0; n < 8; n++) {
                tm0 = fmaxf(tm0, fmaxf(s[n][0], s[n][1]));
                tm1 = fmaxf(tm1, fmaxf(s[n][2], s[n][3]));
            }
            tm0 = fmaxf(tm0, __shfl_xor_sync(0xFFFFFFFF, tm0, 1));
            tm0 = fmaxf(tm0, __shfl_xor_sync(0xFFFFFFFF, tm0, 2));
            tm1 = fmaxf(tm1, __shfl_xor_sync(0xFFFFFFFF, tm1, 1));
            tm1 = fmaxf(tm1, __shfl_xor_sync(0xFFFFFFFF, tm1, 2));

            float mn0 = fmaxf(m0, tm0), mn1 = fmaxf(m1, tm1);
            float corr0 = __expf(m0 - mn0), corr1 = __expf(m1 - mn1);
            m0 = mn0; m1 = mn1;

            float sum0 = 0.0f, sum1 = 0.0f;
#pragma unroll
            for (int n = 0; n < 8; n++) {
                s[n][0] = __expf(s[n][0] - mn0);
                s[n][1] = __expf(s[n][1] - mn0);
                s[n][2] = __expf(s[n][2] - mn1);
                s[n][3] = __expf(s[n][3] - mn1);
                sum0 += s[n][0] + s[n][1];
                sum1 += s[n][2] + s[n][3];
            }
            sum0 += __shfl_xor_sync(0xFFFFFFFF, sum0, 1);
            sum0 += __shfl_xor_sync(0xFFFFFFFF, sum0, 2);
            sum1 += __shfl_xor_sync(0xFFFFFFFF, sum1, 1);
            sum1 += __shfl_xor_sync(0xFFFFFFFF, sum1, 2);
            l0 = l0 * corr0 + sum0;
            l1 = l1 * corr1 + sum1;

#pragma unroll
            for (int n = 0; n < 8; n++) {
                O[n][0] *= corr0; O[n][1] *= corr0;
                O[n][2] *= corr1; O[n][3] *= corr1;
            }

            uint32_t ph[8][2], pl[8][2];
#pragma unroll
            for (int n = 0; n < 8; n++) {
                ph[n][0] = packh2(s[n][0], s[n][1]);
                ph[n][1] = packh2(s[n][2], s[n][3]);
                pl[n][0] = packh2_lo(s[n][0], s[n][1]);
                pl[n][1] = packh2_lo(s[n][2], s[n][3]);
            }

#pragma unroll
            for (int n = 0; n < 8; n++) {
#pragma unroll
                for (int kt = 0; kt < 4; kt++) {
                    uint32_t vh2[2], vl2[2];
                    uint32_t vo = (vt_off + (uint32_t)kt * 16 * ASTR + n * 8) * 2;
                    LDSM2T(vh2, sVh + vo);
                    LDSM2T(vl2, sVl + vo);
                    uint32_t aH[4] = {ph[2 * kt][0], ph[2 * kt][1],
                                      ph[2 * kt + 1][0], ph[2 * kt + 1][1]};
                    uint32_t aL[4] = {pl[2 * kt][0], pl[2 * kt][1],
                                      pl[2 * kt + 1][0], pl[2 * kt + 1][1]};
                    MMAH(O[n], aH, vh2);
                    MMAH(O[n], aL, vh2);
                    MMAH(O[n], aH, vl2);
                }
            }
        }
        __syncthreads();
    }

    float inv0 = 1.0f / l0, inv1 = 1.0f / l1;
    int r0 = b * S_ + q0 + warp_m + gid;
#pragma unroll
    for (int n = 0; n < 8; n++) {
        float o0 = O[n][0] * inv0, o1 = O[n][1] * inv0;
        float o2 = O[n][2] * inv1, o3 = O[n][3] * inv1;
        size_t i0 = (size_t)r0 * D_ + h * HD_ + n * 8 + 2 * tig;
        size_t i1 = (size_t)(r0 + 8) * D_ + h * HD_ + n * 8 + 2 * tig;
        *(uint32_t*)&ohi[i0] = (uint32_t)f16_hi(o0) | ((uint32_t)f16_hi(o1) << 16);
        *(uint32_t*)&olo[i0] = (uint32_t)f16_lo(o0) | ((uint32_t)f16_lo(o1) << 16);
        *(uint32_t*)&ohi[i1] = (uint32_t)f16_hi(o2) | ((uint32_t)f16_hi(o3) << 16);
        *(uint32_t*)&olo[i1] = (uint32_t)f16_lo(o2) | ((uint32_t)f16_lo(o3) << 16);
    }
}

// ---------------- embedding + PE (+ split) ----------------
__global__ void embed_kernel(const int* __restrict__ tokens,
                             const float* __restrict__ emb,
                             float* __restrict__ x,
                             u16* __restrict__ xhi, u16* __restrict__ xlo) {
    int i = blockIdx.x * blockDim.x + threadIdx.x;
    if (i >= M_ * D_) return;
    int m = i / D_, d = i % D_;
    int s = m % S_;
    int tok = tokens[m];
    float expo = (float)(d & ~1) * (-logf(10000.0f) / (float)D_);
    float ang = (float)s * expf(expo);
    float pe = (d & 1) ? cosf(ang) : sinf(ang);
    float v = emb[tok * D_ + d] + pe;
    x[i] = v;
    xhi[i] = f16_hi(v);
    xlo[i] = f16_lo(v);
}

// ---------------- repack QKV weights -> [3D][D] fp16 ----------------
__global__ void repack_qkvT_h(const float* __restrict__ Wq,
                              const float* __restrict__ Wk,
                              const float* __restrict__ Wv,
                              u16* __restrict__ w) {
    int i = blockIdx.x * blockDim.x + threadIdx.x;
    if (i >= D_ * D_) return;
    int n = i / D_, d = i % D_;
    int h = n / HD_, e = n % HD_;
    int src = h * D_ * HD_ + d * HD_ + e;
    size_t iq = (size_t)n * D_ + d;
    w[iq] = f16_hi(Wq[src]);
    w[iq + (size_t)D_ * D_] = f16_hi(Wk[src]);
    w[iq + (size_t)2 * D_ * D_] = f16_hi(Wv[src]);
}

// ---------------- transpose to fp16 ----------------
__global__ void transpose_h(const float* __restrict__ in,
                            u16* __restrict__ o, int R, int C) {
    __shared__ float tile[32][33];
    int c0 = blockIdx.x * 32, r0 = blockIdx.y * 32;
    int x = threadIdx.x, y = threadIdx.y;
#pragma unroll
    for (int i = 0; i < 32; i += 8)
        tile[y + i][x] = in[(size_t)(r0 + y + i) * C + c0 + x];
    __syncthreads();
#pragma unroll
    for (int i = 0; i < 32; i += 8)
        o[(size_t)(c0 + y + i) * R + r0 + x] = f16_hi(tile[x][y + i]);
}

// ---------------- plain fp16 convert (head_W) ----------------
__global__ void conv_h(const float* __restrict__ in, u16* __restrict__ o, int n) {
    int i = blockIdx.x * blockDim.x + threadIdx.x;
    if (i >= n) return;
    o[i] = f16_hi(in[i]);
}

// ---------------- residual + LayerNorm (+ split) ----------------
__global__ __launch_bounds__(128)
void ln_kernel(float* __restrict__ x, const float* __restrict__ delta,
               const float* __restrict__ gamma, const float* __restrict__ beta,
               u16* __restrict__ xhi, u16* __restrict__ xlo) {
    int row = blockIdx.x;
    int tid = threadIdx.x;
    __shared__ float red[128];

    float v[4];
    float s = 0.0f;
#pragma unroll
    for (int i = 0; i < 4; i++) {
        int d = i * 128 + tid;
        float t = x[(size_t)row * D_ + d];
        if (delta) t += delta[(size_t)row * D_ + d];
        v[i] = t;
        s += t;
    }
    red[tid] = s;
    __syncthreads();
    for (int off = 64; off > 0; off >>= 1) {
        if (tid < off) red[tid] += red[tid + off];
        __syncthreads();
    }
    float mean = red[0] * (1.0f / D_);
    __syncthreads();

    float s2 = 0.0f;
#pragma unroll
    for (int i = 0; i < 4; i++) {
        float dv = v[i] - mean;
        s2 += dv * dv;
    }
    red[tid] = s2;
    __syncthreads();
    for (int off = 64; off > 0; off >>= 1) {
        if (tid < off) red[tid] += red[tid + off];
        __syncthreads();
    }
    float var = red[0] * (1.0f / D_);
    float rstd = rsqrtf(var + 1e-5f);
#pragma unroll
    for (int i = 0; i < 4; i++) {
        int d = i * 128 + tid;
        float o = (v[i] - mean) * rstd * gamma[d] + beta[d];
        size_t idx = (size_t)row * D_ + d;
        x[idx] = o;
        xhi[idx] = f16_hi(o);
        xlo[idx] = f16_lo(o);
    }
}

// ---------------- launch ----------------
extern "C" void kernel_launch(void* const* d_in, const int* in_sizes, int n_in,
                              void* d_out, int out_size) {
    const int* tokens    = (const int*)d_in[0];
    const float* emb     = (const float*)d_in[1];
    const float* Wq      = (const float*)d_in[2];
    const float* Wk      = (const float*)d_in[3];
    const float* Wv      = (const float*)d_in[4];
    const float* Wo      = (const float*)d_in[5];
    const float* bo      = (const float*)d_in[6];
    const float* ln1_g   = (const float*)d_in[7];
    const float* ln1_b   = (const float*)d_in[8];
    const float* W1      = (const float*)d_in[9];
    const float* b1      = (const float*)d_in[10];
    const float* W2      = (const float*)d_in[11];
    const float* b2      = (const float*)d_in[12];
    const float* ln2_g   = (const float*)d_in[13];
    const float* ln2_b   = (const float*)d_in[14];
    const float* lnf_g   = (const float*)d_in[15];
    const float* lnf_b   = (const float*)d_in[16];
    const float* head_W  = (const float*)d_in[17];
    float* out = (float*)d_out;

    float *x, *t;
    u16 *qkvhi, *qkvlo, *xhi, *xlo, *ohi, *olo, *hhi, *hlo;
    u16 *wq, *wo, *w1, *w2, *hw;
    cudaGetSymbolAddress((void**)&x, g_x);
    cudaGetSymbolAddress((void**)&t, g_t);
    cudaGetSymbolAddress((void**)&qkvhi, g_qkvhi);
    cudaGetSymbolAddress((void**)&qkvlo, g_qkvlo);
    cudaGetSymbolAddress((void**)&xhi, g_xhi);
    cudaGetSymbolAddress((void**)&xlo, g_xlo);
    cudaGetSymbolAddress((void**)&ohi, g_ohi);
    cudaGetSymbolAddress((void**)&olo, g_olo);
    cudaGetSymbolAddress((void**)&hhi, g_hhi);
    cudaGetSymbolAddress((void**)&hlo, g_hlo);
    cudaGetSymbolAddress((void**)&wq, g_wq);
    cudaGetSymbolAddress((void**)&wo, g_wo);
    cudaGetSymbolAddress((void**)&w1, g_w1);
    cudaGetSymbolAddress((void**)&w2, g_w2);
    cudaGetSymbolAddress((void**)&hw, g_hw);

    cudaFuncSetAttribute((const void*)gemm_f16<false, true>,  cudaFuncAttributeMaxDynamicSharedMemorySize, SMEM_GEMM);
    cudaFuncSetAttribute((const void*)gemm_f16<true, true>,   cudaFuncAttributeMaxDynamicSharedMemorySize, SMEM_GEMM);
    cudaFuncSetAttribute((const void*)gemm_f16<false, false>, cudaFuncAttributeMaxDynamicSharedMemorySize, SMEM_GEMM);
    cudaFuncSetAttribute((const void*)attn_tc, cudaFuncAttributeMaxDynamicSharedMemorySize, SMEM_ATT);

    embed_kernel<<<(M_ * D_ + 255) / 256, 256>>>(tokens, emb, x, xhi, xlo);
    conv_h<<<(V_ * D_ + 255) / 256, 256>>>(head_W, hw, V_ * D_);

    dim3 gQKV(QKV_ / 128, M_ / 128);
    dim3 gD(D_ / 128, M_ / 128);
    dim3 gF(F_ / 128, M_ / 128);
    dim3 gV(V_ / 128, M_ / 128);
    dim3 gAttn(S_ / 128, B_ * H_);
    dim3 tb(32, 8);

    for (int l = 0; l < L_; l++) {
        const float* Wq_l = Wq + (size_t)l * H_ * D_ * HD_;
        const float* Wk_l = Wk + (size_t)l * H_ * D_ * HD_;
        const float* Wv_l = Wv + (size_t)l * H_ * D_ * HD_;
        const float* Wo_l = Wo + (size_t)l * D_ * D_;
        const float* bo_l = bo + (size_t)l * D_;
        const float* W1_l = W1 + (size_t)l * D_ * F_;
        const float* b1_l = b1 + (size_t)l * F_;
        const float* W2_l = W2 + (size_t)l * F_ * D_;
        const float* b2_l = b2 + (size_t)l * D_;

        repack_qkvT_h<<<(D_ * D_ + 255) / 256, 256>>>(Wq_l, Wk_l, Wv_l, wq);
        transpose_h<<<dim3(D_ / 32, D_ / 32), tb>>>(Wo_l, wo, D_, D_);
        transpose_h<<<dim3(F_ / 32, D_ / 32), tb>>>(W1_l, w1, D_, F_);
        transpose_h<<<dim3(D_ / 32, F_ / 32), tb>>>(W2_l, w2, F_, D_);

        gemm_f16<true, true><<<gQKV, 256, SMEM_GEMM>>>(xhi, xlo, wq, nullptr,
                                                       nullptr, qkvhi, qkvlo, M_, QKV_, D_, 0);

        attn_tc<<<gAttn, 256, SMEM_ATT>>>(qkvhi, qkvlo, ohi, olo);

        gemm_f16<false, true><<<gD, 256, SMEM_GEMM>>>(ohi, olo, wo, bo_l,
                                                      t, nullptr, nullptr, M_, D_, D_, 0);
        ln_kernel<<<M_, 128>>>(x, t, ln1_g + (size_t)l * D_, ln1_b + (size_t)l * D_, xhi, xlo);

        gemm_f16<true, true><<<gF, 256, SMEM_GEMM>>>(xhi, xlo, w1, b1_l,
                                                     nullptr, hhi, hlo, M_, F_, D_, 1);
        gemm_f16<false, true><<<gD, 256, SMEM_GEMM>>>(hhi, hlo, w2, b2_l,
                                                      t, nullptr, nullptr, M_, D_, F_, 0);
        ln_kernel<<<M_, 128>>>(x, t, ln2_g + (size_t)l * D_, ln2_b + (size_t)l * D_, xhi, xlo);
    }

    ln_kernel<<<M_, 128>>>(x, nullptr, lnf_g, lnf_b, xhi, xlo);
    // head GEMM: single-pass fp16 (terminal output, no downstream error amplification)
    gemm_f16<false, false><<<gV, 256, SMEM_GEMM>>>(xhi, xlo, hw, nullptr,
                                                   out, nullptr, nullptr, M_, V_, D_, 0);
}

// round 17
// speedup vs baseline: 1.5139x; 1.2999x over previous
#include <cuda_runtime.h>
#include <cuda_fp16.h>
#include <cuda_bf16.h>
#include <math.h>
#include <stdint.h>

#define L_ 4
#define H_ 8
#define D_ 512
#define HD_ 64
#define F_ 2048
#define V_ 32000
#define B_ 2
#define S_ 2048
#define M_ (B_ * S_)
#define QKV_ (3 * D_)

typedef unsigned short u16;

// ---------------- scratch ----------------
__device__ float g_x[M_ * D_];
__device__ float g_t[M_ * D_];
__device__ u16 g_qkvhi[M_ * QKV_], g_qkvlo[M_ * QKV_];
__device__ u16 g_xhi[M_ * D_];
__device__ u16 g_ohi[M_ * D_];
__device__ u16 g_hhi[M_ * F_];
__device__ u16 g_wq[QKV_ * D_];
__device__ u16 g_wo[D_ * D_];
__device__ u16 g_w1[F_ * D_];
__device__ u16 g_w2[D_ * F_];
__device__ u16 g_hw[V_ * D_];

// ---------------- fp16 helpers ----------------
__device__ __forceinline__ u16 f16_hi(float v) {
    __half h = __float2half_rn(v);
    return *(u16*)&h;
}
__device__ __forceinline__ u16 f16_lo(float v) {
    __half h = __float2half_rn(v);
    float r = v - __half2float(h);
    __half l = __float2half_rn(r);
    return *(u16*)&l;
}
__device__ __forceinline__ uint32_t packh2(float a, float b) {
    __half2 t = __halves2half2(__float2half_rn(a), __float2half_rn(b));
    return *(uint32_t*)&t;
}
__device__ __forceinline__ uint32_t packh2_lo(float a, float b) {
    float ra = a - __half2float(__float2half_rn(a));
    float rb = b - __half2float(__float2half_rn(b));
    return packh2(ra, rb);
}

__device__ __forceinline__ uint32_t smem_u32(const void* p) {
    uint32_t a;
    asm("{ .reg .u64 t; cvta.to.shared.u64 t, %1; cvt.u32.u64 %0, t; }"
        : "=r"(a) : "l"(p));
    return a;
}

#define LDSM4(r, addr)                                                          \
    asm volatile("ldmatrix.sync.aligned.m8n8.x4.shared.b16 {%0,%1,%2,%3}, [%4];" \
                 : "=r"((r)[0]), "=r"((r)[1]), "=r"((r)[2]), "=r"((r)[3])        \
                 : "r"(addr))
#define LDSM2(r, addr)                                                          \
    asm volatile("ldmatrix.sync.aligned.m8n8.x2.shared.b16 {%0,%1}, [%2];"       \
                 : "=r"((r)[0]), "=r"((r)[1]) : "r"(addr))
#define LDSM2T(r, addr)                                                         \
    asm volatile("ldmatrix.sync.aligned.m8n8.x2.trans.shared.b16 {%0,%1}, [%2];" \
                 : "=r"((r)[0]), "=r"((r)[1]) : "r"(addr))
#define MMAH(c, a, b)                                                           \
    asm volatile("mma.sync.aligned.m16n8k16.row.col.f32.f16.f16.f32 "            \
                 "{%0,%1,%2,%3}, {%4,%5,%6,%7}, {%8,%9}, {%0,%1,%2,%3};"         \
                 : "+f"((c)[0]), "+f"((c)[1]), "+f"((c)[2]), "+f"((c)[3])        \
                 : "r"((a)[0]), "r"((a)[1]), "r"((a)[2]), "r"((a)[3]),           \
                   "r"((b)[0]), "r"((b)[1]))

// ==================== fp16 mma.sync GEMM (single pass) ====================
// C[M,N] = Ah[M,K] @ Bh[N,K]^T (+bias)(+relu), fp32 accum.
// OMODE: 0 = fp32 out, 1 = split hi+lo out (QKV), 2 = hi-only out (FFN1).
#define KSTRIDE 40
#define MAT_B  (128 * KSTRIDE * 2)   // 10240 B
#define AH_OFF 0
#define BH_OFF MAT_B
#define STG_B  (2 * MAT_B)           // 20480 B
#define NSTG   4
#define SMEM_GEMM (NSTG * STG_B)     // 81920 B

#define CP16(s, g)  asm volatile("cp.async.cg.shared.global [%0], [%1], 16;" :: "r"(s), "l"(g))
#define CP_COMMIT() asm volatile("cp.async.commit_group;" ::: "memory")
#define CP_WAIT2()  asm volatile("cp.async.wait_group 2;" ::: "memory")

template <int OMODE>
__global__ __launch_bounds__(256)
void gemm_f16(const u16* __restrict__ Ah, const u16* __restrict__ Bh,
              const float* __restrict__ bias, float* __restrict__ Cf,
              u16* __restrict__ Chi, u16* __restrict__ Clo,
              int M, int N, int K, int relu) {
    extern __shared__ char sm[];
    uint32_t sb = smem_u32(sm);
    int tid = threadIdx.x, wid = tid >> 5, lane = tid & 31;
    int bm = blockIdx.y * 128, bn = blockIdx.x * 128;
    int warp_m = (wid & 1) * 64, warp_n = (wid >> 1) * 32;

    uint32_t a_off = (uint32_t)(warp_m + (lane & 15)) * KSTRIDE + ((lane >> 4) << 3);
    uint32_t b_off = (uint32_t)(warp_n + (lane & 7)) * KSTRIDE + (((lane >> 3) & 1) << 3);

    int c0i = tid * 2;
    int lrow0 = c0i >> 2, lc0 = (c0i & 3);
    int lrow1 = (c0i + 1) >> 2, lc1 = ((c0i + 1) & 3);

    float acc[4][4][4];
#pragma unroll
    for (int mi = 0; mi < 4; mi++)
#pragma unroll
        for (int ni = 0; ni < 4; ni++)
#pragma unroll
            for (int f = 0; f < 4; f++) acc[mi][ni][f] = 0.0f;

    int nt = K >> 5;

    auto load_stage = [&](int stg, int t) {
        uint32_t ss = sb + (uint32_t)stg * STG_B;
        int k0 = t << 5;
        uint32_t s0 = lrow0 * (KSTRIDE * 2) + lc0 * 16;
        uint32_t s1 = lrow1 * (KSTRIDE * 2) + lc1 * 16;
        size_t ga0 = (size_t)(bm + lrow0) * K + k0 + lc0 * 8;
        size_t ga1 = (size_t)(bm + lrow1) * K + k0 + lc1 * 8;
        size_t gb0 = (size_t)(bn + lrow0) * K + k0 + lc0 * 8;
        size_t gb1 = (size_t)(bn + lrow1) * K + k0 + lc1 * 8;
        CP16(ss + AH_OFF + s0, &Ah[ga0]);
        CP16(ss + AH_OFF + s1, &Ah[ga1]);
        CP16(ss + BH_OFF + s0, &Bh[gb0]);
        CP16(ss + BH_OFF + s1, &Bh[gb1]);
    };

#pragma unroll
    for (int s = 0; s < NSTG - 1; s++) {
        if (s < nt) load_stage(s, s);
        CP_COMMIT();
    }

    for (int t = 0; t < nt; t++) {
        CP_WAIT2();
        __syncthreads();

        uint32_t sa = sb + (uint32_t)(t & (NSTG - 1)) * STG_B;
#pragma unroll
        for (int ks = 0; ks < 2; ks++) {
            uint32_t aoff2 = (a_off + ks * 16) * 2;
            uint32_t boff2 = (b_off + ks * 16) * 2;
            uint32_t ah[4][4], bh[4][2];
#pragma unroll
            for (int mi = 0; mi < 4; mi++)
                LDSM4(ah[mi], sa + AH_OFF + aoff2 + mi * (16 * KSTRIDE * 2));
#pragma unroll
            for (int ni = 0; ni < 4; ni++)
                LDSM2(bh[ni], sa + BH_OFF + boff2 + ni * (8 * KSTRIDE * 2));
#pragma unroll
            for (int mi = 0; mi < 4; mi++)
#pragma unroll
                for (int ni = 0; ni < 4; ni++) MMAH(acc[mi][ni], ah[mi], bh[ni]);
        }

        if (t + NSTG - 1 < nt) load_stage((t + NSTG - 1) & (NSTG - 1), t + NSTG - 1);
        CP_COMMIT();
    }

    int gid = lane >> 2, tig = lane & 3;
#pragma unroll
    for (int mi = 0; mi < 4; mi++) {
        int r0 = bm + warp_m + mi * 16 + gid;
#pragma unroll
        for (int ni = 0; ni < 4; ni++) {
            int cg = bn + warp_n + ni * 8 + tig * 2;
            float c0 = acc[mi][ni][0], c1 = acc[mi][ni][1];
            float c2 = acc[mi][ni][2], c3 = acc[mi][ni][3];
            if (bias) {
                float bx = bias[cg], by = bias[cg + 1];
                c0 += bx; c1 += by; c2 += bx; c3 += by;
            }
            if (relu) {
                c0 = fmaxf(c0, 0.0f); c1 = fmaxf(c1, 0.0f);
                c2 = fmaxf(c2, 0.0f); c3 = fmaxf(c3, 0.0f);
            }
            size_t i0 = (size_t)r0 * N + cg, i1 = (size_t)(r0 + 8) * N + cg;
            if (OMODE == 1) {
                *(uint32_t*)&Chi[i0] = (uint32_t)f16_hi(c0) | ((uint32_t)f16_hi(c1) << 16);
                *(uint32_t*)&Clo[i0] = (uint32_t)f16_lo(c0) | ((uint32_t)f16_lo(c1) << 16);
                *(uint32_t*)&Chi[i1] = (uint32_t)f16_hi(c2) | ((uint32_t)f16_hi(c3) << 16);
                *(uint32_t*)&Clo[i1] = (uint32_t)f16_lo(c2) | ((uint32_t)f16_lo(c3) << 16);
            } else if (OMODE == 2) {
                *(uint32_t*)&Chi[i0] = (uint32_t)f16_hi(c0) | ((uint32_t)f16_hi(c1) << 16);
                *(uint32_t*)&Chi[i1] = (uint32_t)f16_hi(c2) | ((uint32_t)f16_hi(c3) << 16);
            } else {
                *(float2*)&Cf[i0] = make_float2(c0, c1);
                *(float2*)&Cf[i1] = make_float2(c2, c3);
            }
        }
    }
}

// ==================== tensor-core causal attention ====================
// grid (S/128, B*H), 256 threads (8 warps x 16 queries). Internal 3-pass limb math.
#define ASTR 72
#define Q_BUF (128 * ASTR)
#define K_BUF (64 * ASTR)
#define SMEM_ATT ((2 * Q_BUF + 4 * K_BUF) * 2)   // 73728 B

__global__ __launch_bounds__(256)
void attn_tc(const u16* __restrict__ qkvhi, const u16* __restrict__ qkvlo,
             u16* __restrict__ ohi) {
    extern __shared__ u16 sm16[];
    u16* Qh = sm16;
    u16* Ql = Qh + Q_BUF;
    u16* Kh = Ql + Q_BUF;
    u16* Kl = Kh + K_BUF;
    u16* Vh = Kl + K_BUF;
    u16* Vl = Vh + K_BUF;
    uint32_t sQh = smem_u32(Qh), sQl = smem_u32(Ql);
    uint32_t sKh = smem_u32(Kh), sKl = smem_u32(Kl);
    uint32_t sVh = smem_u32(Vh), sVl = smem_u32(Vl);

    int tid = threadIdx.x, wid = tid >> 5, lane = tid & 31;
    int gid = lane >> 2, tig = lane & 3;
    int bh = blockIdx.y;
    int b = bh / H_, h = bh % H_;
    int q0 = blockIdx.x * 128;

    {
        const u16* qh_g = qkvhi + (size_t)(b * S_ + q0) * QKV_ + h * HD_;
        const u16* ql_g = qkvlo + (size_t)(b * S_ + q0) * QKV_ + h * HD_;
        for (int i = tid; i < 128 * 8; i += 256) {
            int r = i >> 3, c = (i & 7) * 8;
            *(uint4*)&Qh[r * ASTR + c] = *(const uint4*)&qh_g[(size_t)r * QKV_ + c];
            *(uint4*)&Ql[r * ASTR + c] = *(const uint4*)&ql_g[(size_t)r * QKV_ + c];
        }
    }

    int warp_m = wid * 16;
    uint32_t qa_off = (uint32_t)(warp_m + (lane & 15)) * ASTR + ((lane >> 4) << 3);
    uint32_t kb_off = (uint32_t)(lane & 7) * ASTR + (((lane >> 3) & 1) << 3);
    uint32_t vt_off = (uint32_t)(lane & 15) * ASTR;

    uint32_t qh[4][4], ql[4][4];
    float m0 = -1e30f, m1 = -1e30f, l0 = 0.0f, l1 = 0.0f;
    float O[8][4];
#pragma unroll
    for (int n = 0; n < 8; n++)
#pragma unroll
        for (int f = 0; f < 4; f++) O[n][f] = 0.0f;

    int ntiles = blockIdx.x * 2 + 2;
    const float sc = 0.125f;

    for (int t = 0; t < ntiles; t++) {
        const u16* kh_g = qkvhi + (size_t)(b * S_ + t * 64) * QKV_ + D_ + h * HD_;
        const u16* kl_g = qkvlo + (size_t)(b * S_ + t * 64) * QKV_ + D_ + h * HD_;
        const u16* vh_g = qkvhi + (size_t)(b * S_ + t * 64) * QKV_ + 2 * D_ + h * HD_;
        const u16* vl_g = qkvlo + (size_t)(b * S_ + t * 64) * QKV_ + 2 * D_ + h * HD_;
        for (int i = tid; i < 64 * 8; i += 256) {
            int r = i >> 3, c = (i & 7) * 8;
            size_t g = (size_t)r * QKV_ + c;
            int so = r * ASTR + c;
            *(uint4*)&Kh[so] = *(const uint4*)&kh_g[g];
            *(uint4*)&Kl[so] = *(const uint4*)&kl_g[g];
            *(uint4*)&Vh[so] = *(const uint4*)&vh_g[g];
            *(uint4*)&Vl[so] = *(const uint4*)&vl_g[g];
        }
        __syncthreads();

        if (t == 0) {
#pragma unroll
            for (int ks = 0; ks < 4; ks++) {
                LDSM4(qh[ks], sQh + (qa_off + ks * 16) * 2);
                LDSM4(ql[ks], sQl + (qa_off + ks * 16) * 2);
            }
        }

        if (t * 64 <= q0 + warp_m + 15) {
            float s[8][4];
#pragma unroll
            for (int n = 0; n < 8; n++) {
#pragma unroll
                for (int f = 0; f < 4; f++) s[n][f] = 0.0f;
#pragma unroll
                for (int ks = 0; ks < 4; ks++) {
                    uint32_t kh2[2], kl2[2];
                    uint32_t ko = (kb_off + (uint32_t)n * 8 * ASTR + ks * 16) * 2;
                    LDSM2(kh2, sKh + ko);
                    LDSM2(kl2, sKl + ko);
                    MMAH(s[n], qh[ks], kh2);
                    MMAH(s[n], ql[ks], kh2);
                    MMAH(s[n], qh[ks], kl2);
                }
            }

            int qg0 = q0 + warp_m + gid, qg1 = qg0 + 8;
#pragma unroll
            for (int n = 0; n < 8; n++) {
                int kc = t * 64 + n * 8 + 2 * tig;
                s[n][0] = (kc > qg0) ? -1e30f : s[n][0] * sc;
                s[n][1] = (kc + 1 > qg0) ? -1e30f : s[n][1] * sc;
                s[n][2] = (kc > qg1) ? -1e30f : s[n][2] * sc;
                s[n][3] = (kc + 1 > qg1) ? -1e30f : s[n][3] * sc;
            }

            float tm0 = -1e30f, tm1 = -1e30f;
#pragma unroll
            for (int n = 0; n < 8; n++) {
                tm0 = fmaxf(tm0, fmaxf(s[n][0], s[n][1]));
                tm1 = fmaxf(tm1, fmaxf(s[n][2], s[n][3]));
            }
            tm0 = fmaxf(tm0, __shfl_xor_sync(0xFFFFFFFF, tm0, 1));
            tm0 = fmaxf(tm0, __shfl_xor_sync(0xFFFFFFFF, tm0, 2));
            tm1 = fmaxf(tm1, __shfl_xor_sync(0xFFFFFFFF, tm1, 1));
            tm1 = fmaxf(tm1, __shfl_xor_sync(0xFFFFFFFF, tm1, 2));

            float mn0 = fmaxf(m0, tm0), mn1 = fmaxf(m1, tm1);
            float corr0 = __expf(m0 - mn0), corr1 = __expf(m1 - mn1);
            m0 = mn0; m1 = mn1;

            float sum0 = 0.0f, sum1 = 0.0f;
#pragma unroll
            for (int n = 0; n < 8; n++) {
                s[n][0] = __expf(s[n][0] - mn0);
                s[n][1] = __expf(s[n][1] - mn0);
                s[n][2] = __expf(s[n][2] - mn1);
                s[n][3] = __expf(s[n][3] - mn1);
                sum0 += s[n][0] + s[n][1];
                sum1 += s[n][2] + s[n][3];
            }
            sum0 += __shfl_xor_sync(0xFFFFFFFF, sum0, 1);
            sum0 += __shfl_xor_sync(0xFFFFFFFF, sum0, 2);
            sum1 += __shfl_xor_sync(0xFFFFFFFF, sum1, 1);
            sum1 += __shfl_xor_sync(0xFFFFFFFF, sum1, 2);
            l0 = l0 * corr0 + sum0;
            l1 = l1 * corr1 + sum1;

#pragma unroll
            for (int n = 0; n < 8; n++) {
                O[n][0] *= corr0; O[n][1] *= corr0;
                O[n][2] *= corr1; O[n][3] *= corr1;
            }

            uint32_t ph[8][2], pl[8][2];
#pragma unroll
            for (int n = 0; n < 8; n++) {
                ph[n][0] = packh2(s[n][0], s[n][1]);
                ph[n][1] = packh2(s[n][2], s[n][3]);
                pl[n][0] = packh2_lo(s[n][0], s[n][1]);
                pl[n][1] = packh2_lo(s[n][2], s[n][3]);
            }

#pragma unroll
            for (int n = 0; n < 8; n++) {
#pragma unroll
                for (int kt = 0; kt < 4; kt++) {
                    uint32_t vh2[2], vl2[2];
                    uint32_t vo = (vt_off + (uint32_t)kt * 16 * ASTR + n * 8) * 2;
                    LDSM2T(vh2, sVh + vo);
                    LDSM2T(vl2, sVl + vo);
                    uint32_t aH[4] = {ph[2 * kt][0], ph[2 * kt][1],
                                      ph[2 * kt + 1][0], ph[2 * kt + 1][1]};
                    uint32_t aL[4] = {pl[2 * kt][0], pl[2 * kt][1],
                                      pl[2 * kt + 1][0], pl[2 * kt + 1][1]};
                    MMAH(O[n], aH, vh2);
                    MMAH(O[n], aL, vh2);
                    MMAH(O[n], aH, vl2);
                }
            }
        }
        __syncthreads();
    }

    float inv0 = 1.0f / l0, inv1 = 1.0f / l1;
    int r0 = b * S_ + q0 + warp_m + gid;
#pragma unroll
    for (int n = 0; n < 8; n++) {
        float o0 = O[n][0] * inv0, o1 = O[n][1] * inv0;
        float o2 = O[n][2] * inv1, o3 = O[n][3] * inv1;
        size_t i0 = (size_t)r0 * D_ + h * HD_ + n * 8 + 2 * tig;
        size_t i1 = (size_t)(r0 + 8) * D_ + h * HD_ + n * 8 + 2 * tig;
        *(uint32_t*)&ohi[i0] = (uint32_t)f16_hi(o0) | ((uint32_t)f16_hi(o1) << 16);
        *(uint32_t*)&ohi[i1] = (uint32_t)f16_hi(o2) | ((uint32_t)f16_hi(o3) << 16);
    }
}

// ---------------- embedding + PE ----------------
__global__ void embed_kernel(const int* __restrict__ tokens,
                             const float* __restrict__ emb,
                             float* __restrict__ x, u16* __restrict__ xhi) {
    int i = blockIdx.x * blockDim.x + threadIdx.x;
    if (i >= M_ * D_) return;
    int m = i / D_, d = i % D_;
    int s = m % S_;
    int tok = tokens[m];
    float expo = (float)(d & ~1) * (-logf(10000.0f) / (float)D_);
    float ang = (float)s * expf(expo);
    float pe = (d & 1) ? cosf(ang) : sinf(ang);
    float v = emb[tok * D_ + d] + pe;
    x[i] = v;
    xhi[i] = f16_hi(v);
}

// ---------------- repack QKV weights -> [3D][D] fp16 ----------------
__global__ void repack_qkvT_h(const float* __restrict__ Wq,
                              const float* __restrict__ Wk,
                              const float* __restrict__ Wv,
                              u16* __restrict__ w) {
    int i = blockIdx.x * blockDim.x + threadIdx.x;
    if (i >= D_ * D_) return;
    int n = i / D_, d = i % D_;
    int h = n / HD_, e = n % HD_;
    int src = h * D_ * HD_ + d * HD_ + e;
    size_t iq = (size_t)n * D_ + d;
    w[iq] = f16_hi(Wq[src]);
    w[iq + (size_t)D_ * D_] = f16_hi(Wk[src]);
    w[iq + (size_t)2 * D_ * D_] = f16_hi(Wv[src]);
}

// ---------------- transpose to fp16 ----------------
__global__ void transpose_h(const float* __restrict__ in,
                            u16* __restrict__ o, int R, int C) {
    __shared__ float tile[32][33];
    int c0 = blockIdx.x * 32, r0 = blockIdx.y * 32;
    int x = threadIdx.x, y = threadIdx.y;
#pragma unroll
    for (int i = 0; i < 32; i += 8)
        tile[y + i][x] = in[(size_t)(r0 + y + i) * C + c0 + x];
    __syncthreads();
#pragma unroll
    for (int i = 0; i < 32; i += 8)
        o[(size_t)(c0 + y + i) * R + r0 + x] = f16_hi(tile[x][y + i]);
}

// ---------------- plain fp16 convert (head_W) ----------------
__global__ void conv_h(const float* __restrict__ in, u16* __restrict__ o, int n) {
    int i = blockIdx.x * blockDim.x + threadIdx.x;
    if (i >= n) return;
    o[i] = f16_hi(in[i]);
}

// ---------------- residual + LayerNorm ----------------
__global__ __launch_bounds__(128)
void ln_kernel(float* __restrict__ x, const float* __restrict__ delta,
               const float* __restrict__ gamma, const float* __restrict__ beta,
               u16* __restrict__ xhi) {
    int row = blockIdx.x;
    int tid = threadIdx.x;
    __shared__ float red[128];

    float v[4];
    float s = 0.0f;
#pragma unroll
    for (int i = 0; i < 4; i++) {
        int d = i * 128 + tid;
        float t = x[(size_t)row * D_ + d];
        if (delta) t += delta[(size_t)row * D_ + d];
        v[i] = t;
        s += t;
    }
    red[tid] = s;
    __syncthreads();
    for (int off = 64; off > 0; off >>= 1) {
        if (tid < off) red[tid] += red[tid + off];
        __syncthreads();
    }
    float mean = red[0] * (1.0f / D_);
    __syncthreads();

    float s2 = 0.0f;
#pragma unroll
    for (int i = 0; i < 4; i++) {
        float dv = v[i] - mean;
        s2 += dv * dv;
    }
    red[tid] = s2;
    __syncthreads();
    for (int off = 64; off > 0; off >>= 1) {
        if (tid < off) red[tid] += red[tid + off];
        __syncthreads();
    }
    float var = red[0] * (1.0f / D_);
    float rstd = rsqrtf(var + 1e-5f);
#pragma unroll
    for (int i = 0; i < 4; i++) {
        int d = i * 128 + tid;
        float o = (v[i] - mean) * rstd * gamma[d] + beta[d];
        size_t idx = (size_t)row * D_ + d;
        x[idx] = o;
        xhi[idx] = f16_hi(o);
    }
}

// ---------------- launch ----------------
extern "C" void kernel_launch(void* const* d_in, const int* in_sizes, int n_in,
                              void* d_out, int out_size) {
    const int* tokens    = (const int*)d_in[0];
    const float* emb     = (const float*)d_in[1];
    const float* Wq      = (const float*)d_in[2];
    const float* Wk      = (const float*)d_in[3];
    const float* Wv      = (const float*)d_in[4];
    const float* Wo      = (const float*)d_in[5];
    const float* bo      = (const float*)d_in[6];
    const float* ln1_g   = (const float*)d_in[7];
    const float* ln1_b   = (const float*)d_in[8];
    const float* W1      = (const float*)d_in[9];
    const float* b1      = (const float*)d_in[10];
    const float* W2      = (const float*)d_in[11];
    const float* b2      = (const float*)d_in[12];
    const float* ln2_g   = (const float*)d_in[13];
    const float* ln2_b   = (const float*)d_in[14];
    const float* lnf_g   = (const float*)d_in[15];
    const float* lnf_b   = (const float*)d_in[16];
    const float* head_W  = (const float*)d_in[17];
    float* out = (float*)d_out;

    float *x, *t;
    u16 *qkvhi, *qkvlo, *xhi, *ohi, *hhi;
    u16 *wq, *wo, *w1, *w2, *hw;
    cudaGetSymbolAddress((void**)&x, g_x);
    cudaGetSymbolAddress((void**)&t, g_t);
    cudaGetSymbolAddress((void**)&qkvhi, g_qkvhi);
    cudaGetSymbolAddress((void**)&qkvlo, g_qkvlo);
    cudaGetSymbolAddress((void**)&xhi, g_xhi);
    cudaGetSymbolAddress((void**)&ohi, g_ohi);
    cudaGetSymbolAddress((void**)&hhi, g_hhi);
    cudaGetSymbolAddress((void**)&wq, g_wq);
    cudaGetSymbolAddress((void**)&wo, g_wo);
    cudaGetSymbolAddress((void**)&w1, g_w1);
    cudaGetSymbolAddress((void**)&w2, g_w2);
    cudaGetSymbolAddress((void**)&hw, g_hw);

    cudaFuncSetAttribute((const void*)gemm_f16<0>, cudaFuncAttributeMaxDynamicSharedMemorySize, SMEM_GEMM);
    cudaFuncSetAttribute((const void*)gemm_f16<1>, cudaFuncAttributeMaxDynamicSharedMemorySize, SMEM_GEMM);
    cudaFuncSetAttribute((const void*)gemm_f16<2>, cudaFuncAttributeMaxDynamicSharedMemorySize, SMEM_GEMM);
    cudaFuncSetAttribute((const void*)attn_tc, cudaFuncAttributeMaxDynamicSharedMemorySize, SMEM_ATT);

    embed_kernel<<<(M_ * D_ + 255) / 256, 256>>>(tokens, emb, x, xhi);
    conv_h<<<(V_ * D_ + 255) / 256, 256>>>(head_W, hw, V_ * D_);

    dim3 gQKV(QKV_ / 128, M_ / 128);
    dim3 gD(D_ / 128, M_ / 128);
    dim3 gF(F_ / 128, M_ / 128);
    dim3 gV(V_ / 128, M_ / 128);
    dim3 gAttn(S_ / 128, B_ * H_);
    dim3 tb(32, 8);

    for (int l = 0; l < L_; l++) {
        const float* Wq_l = Wq + (size_t)l * H_ * D_ * HD_;
        const float* Wk_l = Wk + (size_t)l * H_ * D_ * HD_;
        const float* Wv_l = Wv + (size_t)l * H_ * D_ * HD_;
        const float* Wo_l = Wo + (size_t)l * D_ * D_;
        const float* bo_l = bo + (size_t)l * D_;
        const float* W1_l = W1 + (size_t)l * D_ * F_;
        const float* b1_l = b1 + (size_t)l * F_;
        const float* W2_l = W2 + (size_t)l * F_ * D_;
        const float* b2_l = b2 + (size_t)l * D_;

        repack_qkvT_h<<<(D_ * D_ + 255) / 256, 256>>>(Wq_l, Wk_l, Wv_l, wq);
        transpose_h<<<dim3(D_ / 32, D_ / 32), tb>>>(Wo_l, wo, D_, D_);
        transpose_h<<<dim3(F_ / 32, D_ / 32), tb>>>(W1_l, w1, D_, F_);
        transpose_h<<<dim3(D_ / 32, F_ / 32), tb>>>(W2_l, w2, F_, D_);

        // QKV: 1-pass input, split hi/lo output (attention needs limbs)
        gemm_f16<1><<<gQKV, 256, SMEM_GEMM>>>(xhi, wq, nullptr,
                                              nullptr, qkvhi, qkvlo, M_, QKV_, D_, 0);

        attn_tc<<<gAttn, 256, SMEM_ATT>>>(qkvhi, qkvlo, ohi);

        gemm_f16<0><<<gD, 256, SMEM_GEMM>>>(ohi, wo, bo_l,
                                            t, nullptr, nullptr, M_, D_, D_, 0);
        ln_kernel<<<M_, 128>>>(x, t, ln1_g + (size_t)l * D_, ln1_b + (size_t)l * D_, xhi);

        gemm_f16<2><<<gF, 256, SMEM_GEMM>>>(xhi, w1, b1_l,
                                            nullptr, hhi, nullptr, M_, F_, D_, 1);
        gemm_f16<0><<<gD, 256, SMEM_GEMM>>>(hhi, w2, b2_l,
                                            t, nullptr, nullptr, M_, D_, F_, 0);
        ln_kernel<<<M_, 128>>>(x, t, ln2_g + (size_t)l * D_, ln2_b + (size_t)l * D_, xhi);
    }

    ln_kernel<<<M_, 128>>>(x, nullptr, lnf_g, lnf_b, xhi);
    gemm_f16<0><<<gV, 256, SMEM_GEMM>>>(xhi, hw, nullptr,
                                        out, nullptr, nullptr, M_, V_, D_, 0);
}